// round 1
// baseline (speedup 1.0000x reference)
#include <cuda_runtime.h>

// ---------------------------------------------------------------------------
// MultiHeadAttention: B=8, N=1024, E=768, H=8, d=96
//   q = x@Wq^T + bq   (raw reshape -> head h = contiguous [1024,96] block)
//   energy = q@k^T ; attn = softmax(energy)/sqrt(768) ; out = attn@v
//   final = out@Wp^T + bp
// All GEMMs via tf32 mma.sync.m16n8k8 (fp32 accumulate).
// ---------------------------------------------------------------------------

#define EMB   768
#define SEQN  1024
#define NBAT  8
#define NHEAD 8
#define HDIM  96
#define MTOT  (NBAT * SEQN)   // 8192

// Scratch (device globals: allocation rules forbid cudaMalloc)
__device__ float g_Q[MTOT * EMB];
__device__ float g_K[MTOT * EMB];
__device__ float g_V[MTOT * EMB];
__device__ float g_O[MTOT * EMB];

__device__ __forceinline__ unsigned f2tf(float x) {
    unsigned u;
    asm("cvt.rna.tf32.f32 %0, %1;" : "=r"(u) : "f"(x));
    return u;
}

__device__ __forceinline__ void mma8(float* c,
                                     unsigned a0, unsigned a1, unsigned a2, unsigned a3,
                                     unsigned b0, unsigned b1) {
    asm volatile(
        "mma.sync.aligned.m16n8k8.row.col.f32.tf32.tf32.f32 "
        "{%0,%1,%2,%3},{%4,%5,%6,%7},{%8,%9},{%0,%1,%2,%3};"
        : "+f"(c[0]), "+f"(c[1]), "+f"(c[2]), "+f"(c[3])
        : "r"(a0), "r"(a1), "r"(a2), "r"(a3), "r"(b0), "r"(b1));
}

// ---------------------------------------------------------------------------
// GEMM: C[8192,768] = A[8192,768] @ W[768,768]^T + bias   (NT gemm, tf32)
// Block tile 128x128, BK=32, 256 threads (8 warps, warp tile 64x32).
// ---------------------------------------------------------------------------
__global__ void __launch_bounds__(256) gemm_bias_tf32(
    const float* __restrict__ A, const float* __restrict__ W,
    const float* __restrict__ bias, float* __restrict__ C)
{
    const int K = EMB, N = EMB;
    __shared__ float As[128 * 36];
    __shared__ float Bs[128 * 36];

    int tid  = threadIdx.x;
    int wid  = tid >> 5, lane = tid & 31;
    int g    = lane >> 2, q = lane & 3;
    int wm   = (wid & 1) * 64;     // warp row offset inside block tile
    int wn   = (wid >> 1) * 32;    // warp col offset inside block tile
    int m0   = blockIdx.y * 128;
    int n0   = blockIdx.x * 128;

    float acc[4][4][4];
#pragma unroll
    for (int i = 0; i < 4; i++)
#pragma unroll
        for (int j = 0; j < 4; j++)
#pragma unroll
            for (int r = 0; r < 4; r++) acc[i][j][r] = 0.f;

    for (int kt = 0; kt < K; kt += 32) {
        // cooperative load of A (128x32) and W (128x32) tiles, tf32-converted
#pragma unroll
        for (int i = 0; i < 4; i++) {
            int idx = tid + i * 256;         // float4 index (0..1023)
            int r   = idx >> 3;
            int c4  = (idx & 7) << 2;
            float4 va = *(const float4*)(A + (m0 + r) * K + kt + c4);
            float4 vb = *(const float4*)(W + (n0 + r) * K + kt + c4);
            float4 ta, tb;
            ta.x = __uint_as_float(f2tf(va.x)); ta.y = __uint_as_float(f2tf(va.y));
            ta.z = __uint_as_float(f2tf(va.z)); ta.w = __uint_as_float(f2tf(va.w));
            tb.x = __uint_as_float(f2tf(vb.x)); tb.y = __uint_as_float(f2tf(vb.y));
            tb.z = __uint_as_float(f2tf(vb.z)); tb.w = __uint_as_float(f2tf(vb.w));
            *(float4*)(As + r * 36 + c4) = ta;
            *(float4*)(Bs + r * 36 + c4) = tb;
        }
        __syncthreads();

#pragma unroll
        for (int ks = 0; ks < 4; ks++) {
            int k0 = ks * 8;
            unsigned a[4][4], b[4][2];
#pragma unroll
            for (int ma = 0; ma < 4; ma++) {
                const float* ap = As + (wm + ma * 16 + g) * 36 + k0 + q;
                a[ma][0] = __float_as_uint(ap[0]);
                a[ma][1] = __float_as_uint(ap[8 * 36]);
                a[ma][2] = __float_as_uint(ap[4]);
                a[ma][3] = __float_as_uint(ap[8 * 36 + 4]);
            }
#pragma unroll
            for (int na = 0; na < 4; na++) {
                const float* bp = Bs + (wn + na * 8 + g) * 36 + k0 + q;
                b[na][0] = __float_as_uint(bp[0]);
                b[na][1] = __float_as_uint(bp[4]);
            }
#pragma unroll
            for (int ma = 0; ma < 4; ma++)
#pragma unroll
                for (int na = 0; na < 4; na++)
                    mma8(acc[ma][na], a[ma][0], a[ma][1], a[ma][2], a[ma][3],
                         b[na][0], b[na][1]);
        }
        __syncthreads();
    }

    // epilogue: bias add + store
#pragma unroll
    for (int ma = 0; ma < 4; ma++)
#pragma unroll
        for (int na = 0; na < 4; na++) {
            int r = m0 + wm + ma * 16 + g;
            int c = n0 + wn + na * 8 + 2 * q;
            float b0 = bias[c], b1 = bias[c + 1];
            *(float2*)(C + r * N + c) =
                make_float2(acc[ma][na][0] + b0, acc[ma][na][1] + b1);
            *(float2*)(C + (r + 8) * N + c) =
                make_float2(acc[ma][na][2] + b0, acc[ma][na][3] + b1);
        }
}

// ---------------------------------------------------------------------------
// Flash attention over contiguous head blocks [1024, 96].
// Block: one (b,h) x 128 q-rows. 8 warps, 16 q-rows per warp.
// KV tiles of 64 rows; streaming softmax; /sqrt(768) folded into epilogue.
// ---------------------------------------------------------------------------
#define KSTR 100                    // padded row stride for K/V tiles
#define PSTR 68                     // padded row stride for per-warp P tile
#define ATT_SMEM_BYTES ((2 * 64 * KSTR + 8 * 16 * PSTR) * 4)   // 86016

__global__ void __launch_bounds__(256) attention_kernel()
{
    extern __shared__ float sm[];
    float* Ks = sm;
    float* Vs = sm + 64 * KSTR;
    float* Ps = sm + 2 * 64 * KSTR;

    int bh = blockIdx.x >> 3;       // 0..63 = b*8+h
    int qt = blockIdx.x & 7;
    const float* Qh = g_Q + bh * (SEQN * HDIM);
    const float* Kh = g_K + bh * (SEQN * HDIM);
    const float* Vh = g_V + bh * (SEQN * HDIM);
    float*       Oh = g_O + bh * (SEQN * HDIM);

    int tid = threadIdx.x, wid = tid >> 5, lane = tid & 31;
    int g = lane >> 2, q = lane & 3;
    int qrow = qt * 128 + wid * 16 + g;      // this thread's rows: qrow, qrow+8

    // Q fragments held in registers for the whole kernel (k = 96 -> 12 atoms)
    unsigned qa[12][4];
#pragma unroll
    for (int ka = 0; ka < 12; ka++) {
        const float* p = Qh + qrow * HDIM + ka * 8 + q;
        qa[ka][0] = f2tf(p[0]);
        qa[ka][1] = f2tf(p[8 * HDIM]);
        qa[ka][2] = f2tf(p[4]);
        qa[ka][3] = f2tf(p[8 * HDIM + 4]);
    }

    float m[2] = {-1e30f, -1e30f};
    float l[2] = {0.f, 0.f};
    float oacc[12][4];
#pragma unroll
    for (int na = 0; na < 12; na++)
#pragma unroll
        for (int r = 0; r < 4; r++) oacc[na][r] = 0.f;

    float* Pw = Ps + wid * (16 * PSTR);

    for (int t = 0; t < 16; t++) {
        int kv0 = t * 64;
        // cooperative load of K,V tiles (64 x 96), tf32-converted
#pragma unroll
        for (int i = 0; i < 6; i++) {
            int idx = tid + i * 256;          // 0..1535 float4s
            int r   = idx / 24;
            int c4  = (idx % 24) * 4;
            float4 vk = *(const float4*)(Kh + (kv0 + r) * HDIM + c4);
            float4 vv = *(const float4*)(Vh + (kv0 + r) * HDIM + c4);
            float4 tk, tv;
            tk.x = __uint_as_float(f2tf(vk.x)); tk.y = __uint_as_float(f2tf(vk.y));
            tk.z = __uint_as_float(f2tf(vk.z)); tk.w = __uint_as_float(f2tf(vk.w));
            tv.x = __uint_as_float(f2tf(vv.x)); tv.y = __uint_as_float(f2tf(vv.y));
            tv.z = __uint_as_float(f2tf(vv.z)); tv.w = __uint_as_float(f2tf(vv.w));
            *(float4*)(Ks + r * KSTR + c4) = tk;
            *(float4*)(Vs + r * KSTR + c4) = tv;
        }
        __syncthreads();

        // S = Q @ K^T  (16 x 64 per warp)
        float sacc[8][4];
#pragma unroll
        for (int na = 0; na < 8; na++)
#pragma unroll
            for (int r = 0; r < 4; r++) sacc[na][r] = 0.f;

#pragma unroll
        for (int ks = 0; ks < 12; ks++) {
            int k0 = ks * 8;
#pragma unroll
            for (int na = 0; na < 8; na++) {
                const float* bp = Ks + (na * 8 + g) * KSTR + k0 + q;
                unsigned b0 = __float_as_uint(bp[0]);
                unsigned b1 = __float_as_uint(bp[4]);
                mma8(sacc[na], qa[ks][0], qa[ks][1], qa[ks][2], qa[ks][3], b0, b1);
            }
        }

        // streaming softmax, two row-halves (rows g and g+8)
#pragma unroll
        for (int rh = 0; rh < 2; rh++) {
            float rmax = -1e30f;
#pragma unroll
            for (int na = 0; na < 8; na++)
                rmax = fmaxf(rmax, fmaxf(sacc[na][2 * rh], sacc[na][2 * rh + 1]));
            rmax = fmaxf(rmax, __shfl_xor_sync(0xffffffffu, rmax, 1));
            rmax = fmaxf(rmax, __shfl_xor_sync(0xffffffffu, rmax, 2));
            float mn = fmaxf(m[rh], rmax);

            float rsum = 0.f;
            float* prow = Pw + (g + 8 * rh) * PSTR;
#pragma unroll
            for (int na = 0; na < 8; na++) {
                float p0 = __expf(sacc[na][2 * rh]     - mn);
                float p1 = __expf(sacc[na][2 * rh + 1] - mn);
                rsum += p0 + p1;
                prow[na * 8 + 2 * q]     = __uint_as_float(f2tf(p0));
                prow[na * 8 + 2 * q + 1] = __uint_as_float(f2tf(p1));
            }
            rsum += __shfl_xor_sync(0xffffffffu, rsum, 1);
            rsum += __shfl_xor_sync(0xffffffffu, rsum, 2);

            float sc = __expf(m[rh] - mn);
            l[rh] = l[rh] * sc + rsum;
            m[rh] = mn;
#pragma unroll
            for (int na = 0; na < 12; na++) {
                oacc[na][2 * rh]     *= sc;
                oacc[na][2 * rh + 1] *= sc;
            }
        }
        __syncwarp();

        // O += P @ V  (16 x 96 per warp; P re-fragmented from per-warp smem)
#pragma unroll
        for (int k2 = 0; k2 < 8; k2++) {
            unsigned pa0 = __float_as_uint(Pw[g * PSTR + k2 * 8 + q]);
            unsigned pa1 = __float_as_uint(Pw[(g + 8) * PSTR + k2 * 8 + q]);
            unsigned pa2 = __float_as_uint(Pw[g * PSTR + k2 * 8 + q + 4]);
            unsigned pa3 = __float_as_uint(Pw[(g + 8) * PSTR + k2 * 8 + q + 4]);
#pragma unroll
            for (int na = 0; na < 12; na++) {
                const float* vp = Vs + (k2 * 8 + q) * KSTR + na * 8 + g;
                unsigned b0 = __float_as_uint(vp[0]);
                unsigned b1 = __float_as_uint(vp[4 * KSTR]);
                mma8(oacc[na], pa0, pa1, pa2, pa3, b0, b1);
            }
        }
        __syncthreads();
    }

    // epilogue: normalize by l and fold in the post-softmax /sqrt(768)
    const float scale = 0.03608439182435161f;   // 1/sqrt(768)
    float inv0 = scale / l[0];
    float inv1 = scale / l[1];
#pragma unroll
    for (int na = 0; na < 12; na++) {
        int c = na * 8 + 2 * q;
        *(float2*)(Oh + qrow * HDIM + c) =
            make_float2(oacc[na][0] * inv0, oacc[na][1] * inv0);
        *(float2*)(Oh + (qrow + 8) * HDIM + c) =
            make_float2(oacc[na][2] * inv1, oacc[na][3] * inv1);
    }
}

// ---------------------------------------------------------------------------
// kernel_launch: graph-capturable, allocation-free.
// ---------------------------------------------------------------------------
extern "C" void kernel_launch(void* const* d_in, const int* in_sizes, int n_in,
                              void* d_out, int out_size)
{
    const float* x  = (const float*)d_in[0];
    const float* Wq = (const float*)d_in[1];
    const float* bq = (const float*)d_in[2];
    const float* Wk = (const float*)d_in[3];
    const float* bk = (const float*)d_in[4];
    const float* Wv = (const float*)d_in[5];
    const float* bv = (const float*)d_in[6];
    const float* Wp = (const float*)d_in[7];
    const float* bp = (const float*)d_in[8];
    float* out = (float*)d_out;

    float *pQ, *pK, *pV, *pO;
    cudaGetSymbolAddress((void**)&pQ, g_Q);
    cudaGetSymbolAddress((void**)&pK, g_K);
    cudaGetSymbolAddress((void**)&pV, g_V);
    cudaGetSymbolAddress((void**)&pO, g_O);

    cudaFuncSetAttribute(attention_kernel,
                         cudaFuncAttributeMaxDynamicSharedMemorySize,
                         ATT_SMEM_BYTES);

    dim3 gb(256);
    dim3 gg(EMB / 128, MTOT / 128);   // (6, 64)

    gemm_bias_tf32<<<gg, gb>>>(x, Wq, bq, pQ);
    gemm_bias_tf32<<<gg, gb>>>(x, Wk, bk, pK);
    gemm_bias_tf32<<<gg, gb>>>(x, Wv, bv, pV);
    attention_kernel<<<NBAT * NHEAD * (SEQN / 128), 256, ATT_SMEM_BYTES>>>();
    gemm_bias_tf32<<<gg, gb>>>(pO, Wp, bp, out);
}

// round 3
// speedup vs baseline: 1.4496x; 1.4496x over previous
#include <cuda_runtime.h>

// ---------------------------------------------------------------------------
// MultiHeadAttention: B=8, N=1024, E=768, H=8, d=96  (fp32 in/out)
// tf32 mma.sync.m16n8k8. cp.async double-buffered tiles (raw fp32 bytes);
// RNA rounding to tf32 applied at fragment load via  u + 0x1000  (the MMA HW
// truncates the low 13 bits, so add-half = round-to-nearest-away == cvt.rna).
// ---------------------------------------------------------------------------

#define EMB   768
#define SEQN  1024
#define NBAT  8
#define NHEAD 8
#define HDIM  96
#define MTOT  (NBAT * SEQN)   // 8192

__device__ float g_Q[MTOT * EMB];
__device__ float g_K[MTOT * EMB];
__device__ float g_V[MTOT * EMB];
__device__ float g_O[MTOT * EMB];

__device__ __forceinline__ unsigned sa32(const void* p) {
    return (unsigned)__cvta_generic_to_shared(p);
}
#define CP16(dst, src) \
    asm volatile("cp.async.cg.shared.global [%0], [%1], 16;" :: "r"(dst), "l"(src))
#define CP_COMMIT() asm volatile("cp.async.commit_group;")
#define CP_WAIT1()  asm volatile("cp.async.wait_group 1;")
#define CP_WAIT0()  asm volatile("cp.async.wait_group 0;")

// RNA round-to-tf32 (hardware drops low 13 bits; +half rounds to nearest-away)
__device__ __forceinline__ unsigned rna(float x) {
    return __float_as_uint(x) + 0x1000u;
}

__device__ __forceinline__ void mma8(float* c,
                                     unsigned a0, unsigned a1, unsigned a2, unsigned a3,
                                     unsigned b0, unsigned b1) {
    asm volatile(
        "mma.sync.aligned.m16n8k8.row.col.f32.tf32.tf32.f32 "
        "{%0,%1,%2,%3},{%4,%5,%6,%7},{%8,%9},{%0,%1,%2,%3};"
        : "+f"(c[0]), "+f"(c[1]), "+f"(c[2]), "+f"(c[3])
        : "r"(a0), "r"(a1), "r"(a2), "r"(a3), "r"(b0), "r"(b1));
}

// ---------------------------------------------------------------------------
// GEMM body: C[8192,768] = A[8192,768] @ W[768,768]^T + bias  (NT, tf32)
// Block 128x128, BK=32, 2-stage cp.async pipeline, 256 threads (8 warps).
// ---------------------------------------------------------------------------
#define GSA   (128 * 36)
#define GSTG  (2 * GSA)
#define GEMM_SMEM_BYTES (2 * GSTG * 4)

__device__ __forceinline__ void gemm_body(const float* __restrict__ A,
                                          const float* __restrict__ W,
                                          const float* __restrict__ bias,
                                          float* __restrict__ C)
{
    extern __shared__ float sm[];
    const int K = EMB, N = EMB;
    int tid = threadIdx.x;
    int wid = tid >> 5, lane = tid & 31;
    int g = lane >> 2, q = lane & 3;
    int wm = (wid & 1) * 64;
    int wn = (wid >> 1) * 32;
    int m0 = blockIdx.y * 128;
    int n0 = blockIdx.x * 128;

    int lc4 = (tid & 7) << 2;
    int lr0 = tid >> 3;

    float acc[4][4][4];
#pragma unroll
    for (int i = 0; i < 4; i++)
#pragma unroll
        for (int j = 0; j < 4; j++)
#pragma unroll
            for (int r = 0; r < 4; r++) acc[i][j][r] = 0.f;

    {
        float* as = sm;
        float* bs = sm + GSA;
#pragma unroll
        for (int i = 0; i < 4; i++) {
            int r = lr0 + i * 32;
            CP16(sa32(as + r * 36 + lc4), A + (size_t)(m0 + r) * K + lc4);
            CP16(sa32(bs + r * 36 + lc4), W + (size_t)(n0 + r) * K + lc4);
        }
        CP_COMMIT();
    }

    for (int it = 0; it < 24; it++) {
        if (it + 1 < 24) {
            int s = (it + 1) & 1;
            int kt = (it + 1) * 32;
            float* as = sm + s * GSTG;
            float* bs = as + GSA;
#pragma unroll
            for (int i = 0; i < 4; i++) {
                int r = lr0 + i * 32;
                CP16(sa32(as + r * 36 + lc4), A + (size_t)(m0 + r) * K + kt + lc4);
                CP16(sa32(bs + r * 36 + lc4), W + (size_t)(n0 + r) * K + kt + lc4);
            }
            CP_COMMIT();
            CP_WAIT1();
        } else {
            CP_WAIT0();
        }
        __syncthreads();

        const float* as = sm + (it & 1) * GSTG;
        const float* bs = as + GSA;
#pragma unroll
        for (int ks = 0; ks < 4; ks++) {
            int k0 = ks * 8;
            unsigned a[4][4], b[4][2];
#pragma unroll
            for (int ma = 0; ma < 4; ma++) {
                const float* ap = as + (wm + ma * 16 + g) * 36 + k0 + q;
                a[ma][0] = rna(ap[0]);
                a[ma][1] = rna(ap[8 * 36]);
                a[ma][2] = rna(ap[4]);
                a[ma][3] = rna(ap[8 * 36 + 4]);
            }
#pragma unroll
            for (int na = 0; na < 4; na++) {
                const float* bp = bs + (wn + na * 8 + g) * 36 + k0 + q;
                b[na][0] = rna(bp[0]);
                b[na][1] = rna(bp[4]);
            }
#pragma unroll
            for (int ma = 0; ma < 4; ma++)
#pragma unroll
                for (int na = 0; na < 4; na++)
                    mma8(acc[ma][na], a[ma][0], a[ma][1], a[ma][2], a[ma][3],
                         b[na][0], b[na][1]);
        }
        __syncthreads();
    }

#pragma unroll
    for (int ma = 0; ma < 4; ma++)
#pragma unroll
        for (int na = 0; na < 4; na++) {
            int r = m0 + wm + ma * 16 + g;
            int c = n0 + wn + na * 8 + 2 * q;
            float b0 = bias[c], b1 = bias[c + 1];
            *(float2*)(C + (size_t)r * N + c) =
                make_float2(acc[ma][na][0] + b0, acc[ma][na][1] + b1);
            *(float2*)(C + (size_t)(r + 8) * N + c) =
                make_float2(acc[ma][na][2] + b0, acc[ma][na][3] + b1);
        }
}

__global__ void __launch_bounds__(256, 2) qkv_gemm(
    const float* __restrict__ x,
    const float* __restrict__ Wq, const float* __restrict__ bq,
    const float* __restrict__ Wk, const float* __restrict__ bk,
    const float* __restrict__ Wv, const float* __restrict__ bv,
    float* __restrict__ Q, float* __restrict__ K, float* __restrict__ V)
{
    const float* W; const float* bias; float* C;
    if (blockIdx.z == 0)      { W = Wq; bias = bq; C = Q; }
    else if (blockIdx.z == 1) { W = Wk; bias = bk; C = K; }
    else                      { W = Wv; bias = bv; C = V; }
    gemm_body(x, W, bias, C);
}

__global__ void __launch_bounds__(256, 2) proj_gemm(
    const float* __restrict__ A, const float* __restrict__ W,
    const float* __restrict__ bias, float* __restrict__ C)
{
    gemm_body(A, W, bias, C);
}

// ---------------------------------------------------------------------------
// Flash attention over contiguous head blocks [1024, 96].
// Block = one (b,h) x 128 q-rows; 8 warps x 16 q-rows; KV tiles of 64 rows,
// 2-stage cp.async pipeline. K stride 100 (banks 4g+q), V stride 104
// (banks 8q+g) -> fragment loads conflict-free.
// ---------------------------------------------------------------------------
#define KSTR 100
#define VSTR 104
#define PSTR 68
#define KTILE (64 * KSTR)
#define VTILE (64 * VSTR)
#define ATT_SMEM_BYTES ((2 * KTILE + 2 * VTILE + 8 * 16 * PSTR) * 4)

__global__ void __launch_bounds__(256, 1) attention_kernel()
{
    extern __shared__ float sm[];
    float* Kst = sm;
    float* Vst = sm + 2 * KTILE;
    float* Ps  = sm + 2 * KTILE + 2 * VTILE;

    int bh = blockIdx.x >> 3;
    int qt = blockIdx.x & 7;
    const float* Qh = g_Q + (size_t)bh * (SEQN * HDIM);
    const float* Kh = g_K + (size_t)bh * (SEQN * HDIM);
    const float* Vh = g_V + (size_t)bh * (SEQN * HDIM);
    float*       Oh = g_O + (size_t)bh * (SEQN * HDIM);

    int tid = threadIdx.x, wid = tid >> 5, lane = tid & 31;
    int g = lane >> 2, q = lane & 3;
    int qrow = qt * 128 + wid * 16 + g;

    {
        float* ks = Kst; float* vs = Vst;
#pragma unroll
        for (int i = 0; i < 6; i++) {
            int idx = tid + i * 256;
            int r = idx / 24;
            int c = (idx % 24) * 4;
            CP16(sa32(ks + r * KSTR + c), Kh + r * HDIM + c);
            CP16(sa32(vs + r * VSTR + c), Vh + r * HDIM + c);
        }
        CP_COMMIT();
    }

    // Q fragments, RNA-rounded once, held in registers all kernel
    unsigned qa[12][4];
#pragma unroll
    for (int ka = 0; ka < 12; ka++) {
        const float* p = Qh + (size_t)qrow * HDIM + ka * 8 + q;
        qa[ka][0] = rna(p[0]);
        qa[ka][1] = rna(p[8 * HDIM]);
        qa[ka][2] = rna(p[4]);
        qa[ka][3] = rna(p[8 * HDIM + 4]);
    }

    float m[2] = {-1e30f, -1e30f};
    float l[2] = {0.f, 0.f};
    float oacc[12][4];
#pragma unroll
    for (int na = 0; na < 12; na++)
#pragma unroll
        for (int r = 0; r < 4; r++) oacc[na][r] = 0.f;

    float* Pw = Ps + wid * (16 * PSTR);

    for (int t = 0; t < 16; t++) {
        if (t + 1 < 16) {
            int s = (t + 1) & 1;
            int kv0 = (t + 1) * 64;
            float* ks = Kst + s * KTILE;
            float* vs = Vst + s * VTILE;
#pragma unroll
            for (int i = 0; i < 6; i++) {
                int idx = tid + i * 256;
                int r = idx / 24;
                int c = (idx % 24) * 4;
                CP16(sa32(ks + r * KSTR + c), Kh + (size_t)(kv0 + r) * HDIM + c);
                CP16(sa32(vs + r * VSTR + c), Vh + (size_t)(kv0 + r) * HDIM + c);
            }
            CP_COMMIT();
            CP_WAIT1();
        } else {
            CP_WAIT0();
        }
        __syncthreads();

        const float* Ks = Kst + (t & 1) * KTILE;
        const float* Vs = Vst + (t & 1) * VTILE;

        // S = Q @ K^T  (16 x 64 per warp)
        float sacc[8][4];
#pragma unroll
        for (int na = 0; na < 8; na++)
#pragma unroll
            for (int r = 0; r < 4; r++) sacc[na][r] = 0.f;

#pragma unroll
        for (int ks = 0; ks < 12; ks++) {
            int k0 = ks * 8;
#pragma unroll
            for (int na = 0; na < 8; na++) {
                const float* bp = Ks + (na * 8 + g) * KSTR + k0 + q;
                unsigned b0 = rna(bp[0]);
                unsigned b1 = rna(bp[4]);
                mma8(sacc[na], qa[ks][0], qa[ks][1], qa[ks][2], qa[ks][3], b0, b1);
            }
        }

        // streaming softmax (rows g and g+8)
#pragma unroll
        for (int rh = 0; rh < 2; rh++) {
            float rmax = -1e30f;
#pragma unroll
            for (int na = 0; na < 8; na++)
                rmax = fmaxf(rmax, fmaxf(sacc[na][2 * rh], sacc[na][2 * rh + 1]));
            rmax = fmaxf(rmax, __shfl_xor_sync(0xffffffffu, rmax, 1));
            rmax = fmaxf(rmax, __shfl_xor_sync(0xffffffffu, rmax, 2));
            float mn = fmaxf(m[rh], rmax);

            float rsum = 0.f;
            float* prow = Pw + (g + 8 * rh) * PSTR;
#pragma unroll
            for (int na = 0; na < 8; na++) {
                float p0 = __expf(sacc[na][2 * rh]     - mn);
                float p1 = __expf(sacc[na][2 * rh + 1] - mn);
                rsum += p0 + p1;
                *(float2*)(prow + na * 8 + 2 * q) = make_float2(p0, p1);
            }
            rsum += __shfl_xor_sync(0xffffffffu, rsum, 1);
            rsum += __shfl_xor_sync(0xffffffffu, rsum, 2);

            float sc = __expf(m[rh] - mn);
            l[rh] = l[rh] * sc + rsum;
            m[rh] = mn;
#pragma unroll
            for (int na = 0; na < 12; na++) {
                oacc[na][2 * rh]     *= sc;
                oacc[na][2 * rh + 1] *= sc;
            }
        }
        __syncwarp();

        // O += P @ V  (16 x 96 per warp)
#pragma unroll
        for (int k2 = 0; k2 < 8; k2++) {
            unsigned pa0 = rna(Pw[g * PSTR + k2 * 8 + q]);
            unsigned pa1 = rna(Pw[(g + 8) * PSTR + k2 * 8 + q]);
            unsigned pa2 = rna(Pw[g * PSTR + k2 * 8 + q + 4]);
            unsigned pa3 = rna(Pw[(g + 8) * PSTR + k2 * 8 + q + 4]);
#pragma unroll
            for (int na = 0; na < 12; na++) {
                const float* vp = Vs + (k2 * 8 + q) * VSTR + na * 8 + g;
                unsigned b0 = rna(vp[0]);
                unsigned b1 = rna(vp[4 * VSTR]);
                mma8(oacc[na], pa0, pa1, pa2, pa3, b0, b1);
            }
        }
        __syncthreads();
    }

    const float scale = 0.03608439182435161f;   // 1/sqrt(768)
    float inv0 = scale / l[0];
    float inv1 = scale / l[1];
#pragma unroll
    for (int na = 0; na < 12; na++) {
        int c = na * 8 + 2 * q;
        *(float2*)(Oh + (size_t)qrow * HDIM + c) =
            make_float2(oacc[na][0] * inv0, oacc[na][1] * inv0);
        *(float2*)(Oh + (size_t)(qrow + 8) * HDIM + c) =
            make_float2(oacc[na][2] * inv1, oacc[na][3] * inv1);
    }
}

// ---------------------------------------------------------------------------
extern "C" void kernel_launch(void* const* d_in, const int* in_sizes, int n_in,
                              void* d_out, int out_size)
{
    const float* x  = (const float*)d_in[0];
    const float* Wq = (const float*)d_in[1];
    const float* bq = (const float*)d_in[2];
    const float* Wk = (const float*)d_in[3];
    const float* bk = (const float*)d_in[4];
    const float* Wv = (const float*)d_in[5];
    const float* bv = (const float*)d_in[6];
    const float* Wp = (const float*)d_in[7];
    const float* bp = (const float*)d_in[8];
    float* out = (float*)d_out;

    float *pQ, *pK, *pV, *pO;
    cudaGetSymbolAddress((void**)&pQ, g_Q);
    cudaGetSymbolAddress((void**)&pK, g_K);
    cudaGetSymbolAddress((void**)&pV, g_V);
    cudaGetSymbolAddress((void**)&pO, g_O);

    cudaFuncSetAttribute(qkv_gemm, cudaFuncAttributeMaxDynamicSharedMemorySize,
                         GEMM_SMEM_BYTES);
    cudaFuncSetAttribute(proj_gemm, cudaFuncAttributeMaxDynamicSharedMemorySize,
                         GEMM_SMEM_BYTES);
    cudaFuncSetAttribute(attention_kernel,
                         cudaFuncAttributeMaxDynamicSharedMemorySize,
                         ATT_SMEM_BYTES);

    dim3 gb(256);
    qkv_gemm<<<dim3(EMB / 128, MTOT / 128, 3), gb, GEMM_SMEM_BYTES>>>(
        x, Wq, bq, Wk, bk, Wv, bv, pQ, pK, pV);
    attention_kernel<<<NBAT * NHEAD * (SEQN / 128), 256, ATT_SMEM_BYTES>>>();
    proj_gemm<<<dim3(EMB / 128, MTOT / 128), gb, GEMM_SMEM_BYTES>>>(pO, Wp, bp, out);
}

// round 4
// speedup vs baseline: 1.5557x; 1.0732x over previous
#include <cuda_runtime.h>

// ---------------------------------------------------------------------------
// MultiHeadAttention: B=8, N=1024, E=768, H=8, d=96  (fp32 in/out)
// tf32 mma.sync.m16n8k8 + ldmatrix.x4 fragment loads (CUTLASS tf32 pattern).
// RNA-to-tf32 rounding (u+0x1000; HW truncates low 13 bits) applied once per
// value at producer side (GEMM epilogue / P write / O store) -> hot loops are
// rounding-free and bit-identical to applying rna at every fragment load.
// ---------------------------------------------------------------------------

#define EMB   768
#define SEQN  1024
#define NBAT  8
#define NHEAD 8
#define HDIM  96
#define MTOT  (NBAT * SEQN)   // 8192

__device__ float g_Q[MTOT * EMB];
__device__ float g_K[MTOT * EMB];
__device__ float g_V[MTOT * EMB];
__device__ float g_O[MTOT * EMB];

__device__ __forceinline__ unsigned sa32(const void* p) {
    return (unsigned)__cvta_generic_to_shared(p);
}
#define CP16(dst, src) \
    asm volatile("cp.async.cg.shared.global [%0], [%1], 16;" :: "r"(dst), "l"(src))
#define CP_COMMIT() asm volatile("cp.async.commit_group;")
#define CP_WAIT1()  asm volatile("cp.async.wait_group 1;")
#define CP_WAIT0()  asm volatile("cp.async.wait_group 0;")

// RNA round-to-tf32 (hardware drops low 13 bits; +half = round-nearest-away).
__device__ __forceinline__ unsigned rna(float x) {
    return __float_as_uint(x) + 0x1000u;
}
__device__ __forceinline__ float rnaf(float x) {
    return __uint_as_float(__float_as_uint(x) + 0x1000u);
}

__device__ __forceinline__ void mma8(float* c,
                                     unsigned a0, unsigned a1, unsigned a2, unsigned a3,
                                     unsigned b0, unsigned b1) {
    asm volatile(
        "mma.sync.aligned.m16n8k8.row.col.f32.tf32.tf32.f32 "
        "{%0,%1,%2,%3},{%4,%5,%6,%7},{%8,%9},{%0,%1,%2,%3};"
        : "+f"(c[0]), "+f"(c[1]), "+f"(c[2]), "+f"(c[3])
        : "r"(a0), "r"(a1), "r"(a2), "r"(a3), "r"(b0), "r"(b1));
}

// ldmatrix x4: b16 path moves one 32-bit word per lane per matrix.
// reg j <- matrix j; lane l gets word (l%4) of row (l/4) of that matrix.
__device__ __forceinline__ void ldsm4(unsigned& r0, unsigned& r1,
                                      unsigned& r2, unsigned& r3, unsigned addr) {
    asm volatile("ldmatrix.sync.aligned.m8n8.x4.shared.b16 {%0,%1,%2,%3}, [%4];"
                 : "=r"(r0), "=r"(r1), "=r"(r2), "=r"(r3) : "r"(addr));
}

// ---------------------------------------------------------------------------
// GEMM body: C[8192,768] = A[8192,768] @ W[768,768]^T + bias  (NT, tf32)
// Block 128x128, BK=32, 2-stage cp.async, 256 threads, ldmatrix fragments.
// ROUND: apply rna to outputs (for Q/K/V which feed later tf32 mmas).
// ---------------------------------------------------------------------------
#define GSA   (128 * 36)
#define GSTG  (2 * GSA)
#define GEMM_SMEM_BYTES (2 * GSTG * 4)

template <bool ROUND>
__device__ __forceinline__ void gemm_body(const float* __restrict__ A,
                                          const float* __restrict__ W,
                                          const float* __restrict__ bias,
                                          float* __restrict__ C)
{
    extern __shared__ float sm[];
    const int K = EMB, N = EMB;
    int tid = threadIdx.x;
    int wid = tid >> 5, lane = tid & 31;
    int g = lane >> 2, q = lane & 3;
    int wm = (wid & 1) * 64;
    int wn = (wid >> 1) * 32;
    int m0 = blockIdx.y * 128;
    int n0 = blockIdx.x * 128;

    int lc4 = (tid & 7) << 2;
    int lr0 = tid >> 3;

    // ldmatrix lane-constant offsets (floats)
    int j  = lane >> 3, rr = lane & 7;
    int aoff = (wm + (j & 1) * 8 + rr) * 36 + (j >> 1) * 4;   // A pattern
    int boff = (wn + (j >> 1) * 8 + rr) * 36 + (j & 1) * 4;   // B pattern

    float acc[4][4][4];
#pragma unroll
    for (int i = 0; i < 4; i++)
#pragma unroll
        for (int jj = 0; jj < 4; jj++)
#pragma unroll
            for (int r = 0; r < 4; r++) acc[i][jj][r] = 0.f;

    {
        float* as = sm;
        float* bs = sm + GSA;
#pragma unroll
        for (int i = 0; i < 4; i++) {
            int r = lr0 + i * 32;
            CP16(sa32(as + r * 36 + lc4), A + (size_t)(m0 + r) * K + lc4);
            CP16(sa32(bs + r * 36 + lc4), W + (size_t)(n0 + r) * K + lc4);
        }
        CP_COMMIT();
    }

    for (int it = 0; it < 24; it++) {
        if (it + 1 < 24) {
            int s = (it + 1) & 1;
            int kt = (it + 1) * 32;
            float* as = sm + s * GSTG;
            float* bs = as + GSA;
#pragma unroll
            for (int i = 0; i < 4; i++) {
                int r = lr0 + i * 32;
                CP16(sa32(as + r * 36 + lc4), A + (size_t)(m0 + r) * K + kt + lc4);
                CP16(sa32(bs + r * 36 + lc4), W + (size_t)(n0 + r) * K + kt + lc4);
            }
            CP_COMMIT();
            CP_WAIT1();
        } else {
            CP_WAIT0();
        }
        __syncthreads();

        const float* as = sm + (it & 1) * GSTG;
        const float* bs = as + GSA;
        unsigned sa_a = sa32(as) + 4u * aoff;
        unsigned sa_b = sa32(bs) + 4u * boff;

#pragma unroll
        for (int ks = 0; ks < 4; ks++) {
            int k0 = ks * 8;
            unsigned a[4][4], b[4][2];
#pragma unroll
            for (int ma = 0; ma < 4; ma++)
                ldsm4(a[ma][0], a[ma][1], a[ma][2], a[ma][3],
                      sa_a + 4u * (ma * 16 * 36 + k0));
#pragma unroll
            for (int p = 0; p < 2; p++)
                ldsm4(b[2 * p][0], b[2 * p][1], b[2 * p + 1][0], b[2 * p + 1][1],
                      sa_b + 4u * (p * 16 * 36 + k0));
            // rna on raw fragments
#pragma unroll
            for (int ma = 0; ma < 4; ma++)
#pragma unroll
                for (int r = 0; r < 4; r++) a[ma][r] += 0x1000u;
#pragma unroll
            for (int na = 0; na < 4; na++) { b[na][0] += 0x1000u; b[na][1] += 0x1000u; }

#pragma unroll
            for (int ma = 0; ma < 4; ma++)
#pragma unroll
                for (int na = 0; na < 4; na++)
                    mma8(acc[ma][na], a[ma][0], a[ma][1], a[ma][2], a[ma][3],
                         b[na][0], b[na][1]);
        }
        __syncthreads();
    }

#pragma unroll
    for (int ma = 0; ma < 4; ma++)
#pragma unroll
        for (int na = 0; na < 4; na++) {
            int r = m0 + wm + ma * 16 + g;
            int c = n0 + wn + na * 8 + 2 * q;
            float b0 = bias[c], b1 = bias[c + 1];
            float v00 = acc[ma][na][0] + b0, v01 = acc[ma][na][1] + b1;
            float v10 = acc[ma][na][2] + b0, v11 = acc[ma][na][3] + b1;
            if (ROUND) { v00 = rnaf(v00); v01 = rnaf(v01); v10 = rnaf(v10); v11 = rnaf(v11); }
            *(float2*)(C + (size_t)r * N + c)       = make_float2(v00, v01);
            *(float2*)(C + (size_t)(r + 8) * N + c) = make_float2(v10, v11);
        }
}

__global__ void __launch_bounds__(256, 2) qkv_gemm(
    const float* __restrict__ x,
    const float* __restrict__ Wq, const float* __restrict__ bq,
    const float* __restrict__ Wk, const float* __restrict__ bk,
    const float* __restrict__ Wv, const float* __restrict__ bv,
    float* __restrict__ Q, float* __restrict__ K, float* __restrict__ V)
{
    const float* W; const float* bias; float* C;
    if (blockIdx.z == 0)      { W = Wq; bias = bq; C = Q; }
    else if (blockIdx.z == 1) { W = Wk; bias = bk; C = K; }
    else                      { W = Wv; bias = bv; C = V; }
    gemm_body<true>(x, W, bias, C);
}

__global__ void __launch_bounds__(256, 2) proj_gemm(
    const float* __restrict__ A, const float* __restrict__ W,
    const float* __restrict__ bias, float* __restrict__ C)
{
    gemm_body<false>(A, W, bias, C);
}

// ---------------------------------------------------------------------------
// Flash attention over contiguous head blocks [1024, 96].
// Q/K/V pre-rounded to tf32 grid -> no rna in hot loops.
// K & P fragments via ldmatrix.x4; V via conflict-free LDS.32.
// ---------------------------------------------------------------------------
#define KSTR 100
#define VSTR 104
#define PSTR 68
#define KTILE (64 * KSTR)
#define VTILE (64 * VSTR)
#define ATT_SMEM_BYTES ((2 * KTILE + 2 * VTILE + 8 * 16 * PSTR) * 4)

__global__ void __launch_bounds__(256, 1) attention_kernel()
{
    extern __shared__ float sm[];
    float* Kst = sm;
    float* Vst = sm + 2 * KTILE;
    float* Ps  = sm + 2 * KTILE + 2 * VTILE;

    int bh = blockIdx.x >> 3;
    int qt = blockIdx.x & 7;
    const float* Qh = g_Q + (size_t)bh * (SEQN * HDIM);
    const float* Kh = g_K + (size_t)bh * (SEQN * HDIM);
    const float* Vh = g_V + (size_t)bh * (SEQN * HDIM);
    float*       Oh = g_O + (size_t)bh * (SEQN * HDIM);

    int tid = threadIdx.x, wid = tid >> 5, lane = tid & 31;
    int g = lane >> 2, q = lane & 3;
    int qrow = qt * 128 + wid * 16 + g;

    int j  = lane >> 3, rr = lane & 7;
    int kboff = ((j >> 1) * 8 + rr) * KSTR + (j & 1) * 4;   // K: B pattern
    int paoff = ((j & 1) * 8 + rr) * PSTR + (j >> 1) * 4;   // P: A pattern

    {
        float* ks = Kst; float* vs = Vst;
#pragma unroll
        for (int i = 0; i < 6; i++) {
            int idx = tid + i * 256;
            int r = idx / 24;
            int c = (idx % 24) * 4;
            CP16(sa32(ks + r * KSTR + c), Kh + r * HDIM + c);
            CP16(sa32(vs + r * VSTR + c), Vh + r * HDIM + c);
        }
        CP_COMMIT();
    }

    // Q fragments (already tf32-rounded in g_Q)
    unsigned qa[12][4];
#pragma unroll
    for (int ka = 0; ka < 12; ka++) {
        const float* p = Qh + (size_t)qrow * HDIM + ka * 8 + q;
        qa[ka][0] = __float_as_uint(p[0]);
        qa[ka][1] = __float_as_uint(p[8 * HDIM]);
        qa[ka][2] = __float_as_uint(p[4]);
        qa[ka][3] = __float_as_uint(p[8 * HDIM + 4]);
    }

    float m[2] = {-1e30f, -1e30f};
    float l[2] = {0.f, 0.f};
    float oacc[12][4];
#pragma unroll
    for (int na = 0; na < 12; na++)
#pragma unroll
        for (int r = 0; r < 4; r++) oacc[na][r] = 0.f;

    float* Pw = Ps + wid * (16 * PSTR);
    unsigned sa_P = sa32(Pw) + 4u * paoff;

    for (int t = 0; t < 16; t++) {
        if (t + 1 < 16) {
            int s = (t + 1) & 1;
            int kv0 = (t + 1) * 64;
            float* ks = Kst + s * KTILE;
            float* vs = Vst + s * VTILE;
#pragma unroll
            for (int i = 0; i < 6; i++) {
                int idx = tid + i * 256;
                int r = idx / 24;
                int c = (idx % 24) * 4;
                CP16(sa32(ks + r * KSTR + c), Kh + (size_t)(kv0 + r) * HDIM + c);
                CP16(sa32(vs + r * VSTR + c), Vh + (size_t)(kv0 + r) * HDIM + c);
            }
            CP_COMMIT();
            CP_WAIT1();
        } else {
            CP_WAIT0();
        }
        __syncthreads();

        const float* Ks = Kst + (t & 1) * KTILE;
        const float* Vs = Vst + (t & 1) * VTILE;
        unsigned sa_K = sa32(Ks) + 4u * kboff;

        // S = Q @ K^T  (16 x 64 per warp)
        float sacc[8][4];
#pragma unroll
        for (int na = 0; na < 8; na++)
#pragma unroll
            for (int r = 0; r < 4; r++) sacc[na][r] = 0.f;

#pragma unroll
        for (int ks = 0; ks < 12; ks++) {
            int k0 = ks * 8;
#pragma unroll
            for (int p = 0; p < 4; p++) {
                unsigned b00, b01, b10, b11;
                ldsm4(b00, b01, b10, b11, sa_K + 4u * (p * 16 * KSTR + k0));
                mma8(sacc[2 * p],     qa[ks][0], qa[ks][1], qa[ks][2], qa[ks][3], b00, b01);
                mma8(sacc[2 * p + 1], qa[ks][0], qa[ks][1], qa[ks][2], qa[ks][3], b10, b11);
            }
        }

        // streaming softmax (rows g and g+8); P written tf32-rounded
#pragma unroll
        for (int rh = 0; rh < 2; rh++) {
            float rmax = -1e30f;
#pragma unroll
            for (int na = 0; na < 8; na++)
                rmax = fmaxf(rmax, fmaxf(sacc[na][2 * rh], sacc[na][2 * rh + 1]));
            rmax = fmaxf(rmax, __shfl_xor_sync(0xffffffffu, rmax, 1));
            rmax = fmaxf(rmax, __shfl_xor_sync(0xffffffffu, rmax, 2));
            float mn = fmaxf(m[rh], rmax);

            float rsum = 0.f;
            float* prow = Pw + (g + 8 * rh) * PSTR;
#pragma unroll
            for (int na = 0; na < 8; na++) {
                float p0 = __expf(sacc[na][2 * rh]     - mn);
                float p1 = __expf(sacc[na][2 * rh + 1] - mn);
                rsum += p0 + p1;
                *(float2*)(prow + na * 8 + 2 * q) = make_float2(rnaf(p0), rnaf(p1));
            }
            rsum += __shfl_xor_sync(0xffffffffu, rsum, 1);
            rsum += __shfl_xor_sync(0xffffffffu, rsum, 2);

            float sc = __expf(m[rh] - mn);
            l[rh] = l[rh] * sc + rsum;
            m[rh] = mn;
#pragma unroll
            for (int na = 0; na < 12; na++) {
                oacc[na][2 * rh]     *= sc;
                oacc[na][2 * rh + 1] *= sc;
            }
        }
        __syncwarp();

        // O += P @ V  (16 x 96 per warp)
#pragma unroll
        for (int k2 = 0; k2 < 8; k2++) {
            unsigned pa0, pa1, pa2, pa3;
            ldsm4(pa0, pa1, pa2, pa3, sa_P + 4u * (k2 * 8));
#pragma unroll
            for (int na = 0; na < 12; na++) {
                const float* vp = Vs + (k2 * 8 + q) * VSTR + na * 8 + g;
                unsigned b0 = __float_as_uint(vp[0]);
                unsigned b1 = __float_as_uint(vp[4 * VSTR]);
                mma8(oacc[na], pa0, pa1, pa2, pa3, b0, b1);
            }
        }
        __syncthreads();
    }

    // epilogue: normalize, fold /sqrt(768), round to tf32 grid for proj
    const float scale = 0.03608439182435161f;   // 1/sqrt(768)
    float inv0 = scale / l[0];
    float inv1 = scale / l[1];
#pragma unroll
    for (int na = 0; na < 12; na++) {
        int c = na * 8 + 2 * q;
        *(float2*)(Oh + (size_t)qrow * HDIM + c) =
            make_float2(rnaf(oacc[na][0] * inv0), rnaf(oacc[na][1] * inv0));
        *(float2*)(Oh + (size_t)(qrow + 8) * HDIM + c) =
            make_float2(rnaf(oacc[na][2] * inv1), rnaf(oacc[na][3] * inv1));
    }
}

// ---------------------------------------------------------------------------
extern "C" void kernel_launch(void* const* d_in, const int* in_sizes, int n_in,
                              void* d_out, int out_size)
{
    const float* x  = (const float*)d_in[0];
    const float* Wq = (const float*)d_in[1];
    const float* bq = (const float*)d_in[2];
    const float* Wk = (const float*)d_in[3];
    const float* bk = (const float*)d_in[4];
    const float* Wv = (const float*)d_in[5];
    const float* bv = (const float*)d_in[6];
    const float* Wp = (const float*)d_in[7];
    const float* bp = (const float*)d_in[8];
    float* out = (float*)d_out;

    float *pQ, *pK, *pV, *pO;
    cudaGetSymbolAddress((void**)&pQ, g_Q);
    cudaGetSymbolAddress((void**)&pK, g_K);
    cudaGetSymbolAddress((void**)&pV, g_V);
    cudaGetSymbolAddress((void**)&pO, g_O);

    cudaFuncSetAttribute(qkv_gemm, cudaFuncAttributeMaxDynamicSharedMemorySize,
                         GEMM_SMEM_BYTES);
    cudaFuncSetAttribute(proj_gemm, cudaFuncAttributeMaxDynamicSharedMemorySize,
                         GEMM_SMEM_BYTES);
    cudaFuncSetAttribute(attention_kernel,
                         cudaFuncAttributeMaxDynamicSharedMemorySize,
                         ATT_SMEM_BYTES);

    dim3 gb(256);
    qkv_gemm<<<dim3(EMB / 128, MTOT / 128, 3), gb, GEMM_SMEM_BYTES>>>(
        x, Wq, bq, Wk, bk, Wv, bv, pQ, pK, pV);
    attention_kernel<<<NBAT * NHEAD * (SEQN / 128), 256, ATT_SMEM_BYTES>>>();
    proj_gemm<<<dim3(EMB / 128, MTOT / 128), gb, GEMM_SMEM_BYTES>>>(pO, Wp, bp, out);
}